// round 11
// baseline (speedup 1.0000x reference)
#include <cuda_runtime.h>
#include <cuda_fp16.h>
#include <cstdint>

#define NN 100000
#define EE 3200000
#define H 128

// ---------------- scratch (__device__ globals; allocation-free rule) ----------------
__device__ float  g_X[(size_t)NN * H];    // 51.2 MB fp32 ping (head)
__device__ float  g_A[(size_t)NN * H];    // 51.2 MB fp32 pong
__device__ __half g_Xh[(size_t)NN * H];   // 25.6 MB fp16 conv-GEMM output (gather source)
__device__ float  g_dinv[NN];
__device__ int    g_deg[100352];          // padded for int4 zeroing
__device__ int    g_off[NN + 1];
__device__ int    g_cur[100352];
__device__ int    g_csrc[EE];             // CSR: src per incoming edge of dst
__device__ float  g_cnrm[EE];             // CSR: norm per incoming edge
__device__ int    g_is64;

__device__ __forceinline__ float fast_tanh(float x) {
    float t = __expf(-2.0f * fabsf(x));
    float r = __fdividef(1.0f - t, 1.0f + t);
    return copysignf(r, x);
}

// ---------------- edge dtype detection (int32 vs int64) ----------------
__global__ void detect_k(const int* __restrict__ ei32) {
    __shared__ int nz;
    if (threadIdx.x == 0) nz = 0;
    __syncthreads();
    int c = 0;
    for (int k = threadIdx.x; k < 4096; k += blockDim.x)
        if (ei32[2 * k + 1] != 0) c++;
    atomicAdd(&nz, c);
    __syncthreads();
    if (threadIdx.x == 0) g_is64 = (nz == 0) ? 1 : 0;
}

__device__ __forceinline__ int edge_val(const void* ei, long long E, long long idx, int row) {
    if (g_is64) return (int)((const long long*)ei)[row ? E + idx : idx];
    return ((const int*)ei)[row ? E + idx : idx];
}

// ---------------- zero ints ----------------
__global__ void zeroi_k(int4* __restrict__ p, int n4) {
    int i = blockIdx.x * blockDim.x + threadIdx.x;
    if (i < n4) p[i] = make_int4(0, 0, 0, 0);
}

// ---------------- degree count ----------------
__global__ void deg_k(const void* __restrict__ ei, long long E, int* __restrict__ deg) {
    long long e = (long long)blockIdx.x * blockDim.x + threadIdx.x;
    if (e < E) atomicAdd(&deg[edge_val(ei, E, e, 1)], 1);
}

__global__ void dinv_k(const int* __restrict__ deg, float* __restrict__ dinv, int n) {
    int i = blockIdx.x * blockDim.x + threadIdx.x;
    if (i < n) dinv[i] = rsqrtf((float)deg[i] + 2.0f);   // improved self-loop: +2
}

// ---------------- single-block scan: deg -> off, cur ----------------
__global__ void __launch_bounds__(1024) scan_k(const int* __restrict__ deg,
                                               int* __restrict__ off,
                                               int* __restrict__ cur, int n) {
    __shared__ int part[1024];
    int t = threadIdx.x;
    int chunk = (n + 1023) / 1024;
    int lo = t * chunk, hi = lo + chunk < n ? lo + chunk : n;
    int s = 0;
    for (int i = lo; i < hi; i++) s += deg[i];
    part[t] = s;
    __syncthreads();
    for (int o = 1; o < 1024; o <<= 1) {
        int v = (t >= o) ? part[t - o] : 0;
        __syncthreads();
        part[t] += v;
        __syncthreads();
    }
    int base = (t == 0) ? 0 : part[t - 1];
    for (int i = lo; i < hi; i++) {
        off[i] = base; cur[i] = base; base += deg[i];
    }
    if (t == 0) off[n] = part[1023];
}

// ---------------- CSR fill ----------------
__global__ void fill_k(const void* __restrict__ ei, long long E,
                       const float* __restrict__ dinv,
                       int* __restrict__ cur, int* __restrict__ csrc,
                       float* __restrict__ cnrm) {
    long long e = (long long)blockIdx.x * blockDim.x + threadIdx.x;
    if (e >= E) return;
    int s = edge_val(ei, E, e, 0);
    int d = edge_val(ei, E, e, 1);
    int pos = atomicAdd(&cur[d], 1);
    csrc[pos] = s;
    cnrm[pos] = dinv[s] * dinv[d];
}

// ---------------- gather (fp16 rows) + conv epilogue ----------------
// out_fp32 = tanh(sum_edges(norm * xh[src]) + xh[node]*2dinv^2 + b)
// Each lane owns 4 channels = one uint2 (4 halves) per row: 256B/row total.
__global__ void __launch_bounds__(256) aggregate_k(
    const __half* __restrict__ xw, const int* __restrict__ off,
    const int* __restrict__ deg, const int* __restrict__ csrc,
    const float* __restrict__ cnrm, const float* __restrict__ dinv,
    const float* __restrict__ bias, float* __restrict__ out, int n)
{
    int node = (blockIdx.x * 256 + threadIdx.x) >> 5;
    int lane = threadIdx.x & 31;
    if (node >= n) return;
    int j = off[node];
    int end = j + deg[node];
    const uint2* X2 = (const uint2*)xw;   // 8B = 4 halves per lane
    float4 acc = make_float4(0.f, 0.f, 0.f, 0.f);
    for (; j + 1 < end; j += 2) {
        int s0 = __ldg(&csrc[j]);     int s1 = __ldg(&csrc[j + 1]);
        float n0 = __ldg(&cnrm[j]);   float n1 = __ldg(&cnrm[j + 1]);
        uint2 r0 = X2[(size_t)s0 * 32 + lane];
        uint2 r1 = X2[(size_t)s1 * 32 + lane];
        float2 a01 = __half22float2(*(__half2*)&r0.x);
        float2 a23 = __half22float2(*(__half2*)&r0.y);
        float2 b01 = __half22float2(*(__half2*)&r1.x);
        float2 b23 = __half22float2(*(__half2*)&r1.y);
        acc.x = fmaf(a01.x, n0, acc.x); acc.y = fmaf(a01.y, n0, acc.y);
        acc.z = fmaf(a23.x, n0, acc.z); acc.w = fmaf(a23.y, n0, acc.w);
        acc.x = fmaf(b01.x, n1, acc.x); acc.y = fmaf(b01.y, n1, acc.y);
        acc.z = fmaf(b23.x, n1, acc.z); acc.w = fmaf(b23.y, n1, acc.w);
    }
    if (j < end) {
        int s0 = __ldg(&csrc[j]);
        float n0 = __ldg(&cnrm[j]);
        uint2 r0 = X2[(size_t)s0 * 32 + lane];
        float2 a01 = __half22float2(*(__half2*)&r0.x);
        float2 a23 = __half22float2(*(__half2*)&r0.y);
        acc.x = fmaf(a01.x, n0, acc.x); acc.y = fmaf(a01.y, n0, acc.y);
        acc.z = fmaf(a23.x, n0, acc.z); acc.w = fmaf(a23.y, n0, acc.w);
    }
    float di = dinv[node];
    float sw = 2.0f * di * di;
    uint2 rs = X2[(size_t)node * 32 + lane];
    float2 s01 = __half22float2(*(__half2*)&rs.x);
    float2 s23 = __half22float2(*(__half2*)&rs.y);
    float4 bv = ((const float4*)bias)[lane];
    acc.x = fast_tanh(fmaf(s01.x, sw, acc.x) + bv.x);
    acc.y = fast_tanh(fmaf(s01.y, sw, acc.y) + bv.y);
    acc.z = fast_tanh(fmaf(s23.x, sw, acc.z) + bv.z);
    acc.w = fast_tanh(fmaf(s23.y, sw, acc.w) + bv.w);
    ((float4*)out)[(size_t)node * 32 + lane] = acc;
}

// ---------------- tf32 MMA common ----------------
#define ASTRIDE 132
#define WSTRIDE 136
#define TC_SMEM ((128 * ASTRIDE + 128 * WSTRIDE) * 4)

__device__ __forceinline__ float to_tf32(float x) {
    uint32_t u;
    asm("cvt.rna.tf32.f32 %0, %1;" : "=r"(u) : "f"(x));
    return __uint_as_float(u);
}

__device__ __forceinline__ void mma_tf32(float* c, const uint32_t* a,
                                         uint32_t b0, uint32_t b1) {
    asm volatile(
        "mma.sync.aligned.m16n8k8.row.col.f32.tf32.tf32.f32 "
        "{%0,%1,%2,%3}, {%4,%5,%6,%7}, {%8,%9}, {%0,%1,%2,%3};"
        : "+f"(c[0]), "+f"(c[1]), "+f"(c[2]), "+f"(c[3])
        : "r"(a[0]), "r"(a[1]), "r"(a[2]), "r"(a[3]), "r"(b0), "r"(b1));
}

// mainloop over one 128x128 tile
__device__ __forceinline__ void mma_tile_128(
    const float* __restrict__ Asrc, const float* __restrict__ Wn,
    int strip, int nquart, int gid, int tg, float acc[2][4][4])
{
    #pragma unroll
    for (int r = 0; r < 2; r++)
        #pragma unroll
        for (int j = 0; j < 4; j++)
            #pragma unroll
            for (int q = 0; q < 4; q++) acc[r][j][q] = 0.f;

    const float* A0 = Asrc + (strip + gid) * ASTRIDE + tg;
    const float* B0 = Wn + tg * WSTRIDE + nquart + gid;

    #pragma unroll 4
    for (int ks = 0; ks < 16; ks++) {
        int k0 = ks * 8;
        uint32_t a[2][4];
        #pragma unroll
        for (int r = 0; r < 2; r++) {
            const float* p = A0 + r * 16 * ASTRIDE + k0;
            a[r][0] = __float_as_uint(p[0]);
            a[r][1] = __float_as_uint(p[8 * ASTRIDE]);
            a[r][2] = __float_as_uint(p[4]);
            a[r][3] = __float_as_uint(p[8 * ASTRIDE + 4]);
        }
        const float* q = B0 + k0 * WSTRIDE;
        #pragma unroll
        for (int j = 0; j < 4; j++) {
            uint32_t b0 = __float_as_uint(q[j * 8]);
            uint32_t b1 = __float_as_uint(q[4 * WSTRIDE + j * 8]);
            mma_tf32(acc[0][j], a[0], b0, b1);
            mma_tf32(acc[1][j], a[1], b0, b1);
        }
    }
}

// ---------------- GEMM [n,128]@[128,128]; OUTH: half2 output, else fp32(+bias+tanh) ----
template <bool TANH, bool BIAS, bool OUTH>
__global__ void __launch_bounds__(512) gemm_tc(
    const float* __restrict__ in, const float* __restrict__ W,
    const float* __restrict__ bias, float* __restrict__ outf,
    __half* __restrict__ outh, int n)
{
    extern __shared__ float sm[];
    float* Asm = sm;
    float* Wn  = sm + 128 * ASTRIDE;

    int tid = threadIdx.x, lane = tid & 31, w = tid >> 5;
    int nb = blockIdx.x * 128;

    const float4* In4 = (const float4*)in;
    #pragma unroll
    for (int i = tid; i < 4096; i += 512) {
        int row = i >> 5, q = i & 31;
        int node = nb + row < n ? nb + row : n - 1;
        float4 v = In4[(size_t)node * 32 + q];
        v.x = to_tf32(v.x); v.y = to_tf32(v.y);
        v.z = to_tf32(v.z); v.w = to_tf32(v.w);
        *(float4*)(Asm + row * ASTRIDE + q * 4) = v;
    }
    const float4* W4 = (const float4*)W;
    #pragma unroll
    for (int i = tid; i < 4096; i += 512) {
        int k = i >> 5, q = i & 31;
        float4 v = W4[k * 32 + q];
        v.x = to_tf32(v.x); v.y = to_tf32(v.y);
        v.z = to_tf32(v.z); v.w = to_tf32(v.w);
        *(float4*)(Wn + k * WSTRIDE + q * 4) = v;
    }
    __syncthreads();

    int strip  = (w >> 2) * 32;
    int nquart = (w & 3) * 32;
    int gid = lane >> 2, tg = lane & 3;

    float acc[2][4][4];
    mma_tile_128(Asm, Wn, strip, nquart, gid, tg, acc);

    #pragma unroll
    for (int j = 0; j < 4; j++) {
        int col = nquart + 8 * j + 2 * tg;
        float2 bv = BIAS ? __ldg((const float2*)(bias + col)) : make_float2(0.f, 0.f);
        #pragma unroll
        for (int r = 0; r < 2; r++) {
            int row0 = nb + strip + r * 16 + gid;
            int row1 = row0 + 8;
            float v0 = acc[r][j][0] + bv.x;
            float v1 = acc[r][j][1] + bv.y;
            float v2 = acc[r][j][2] + bv.x;
            float v3 = acc[r][j][3] + bv.y;
            if (TANH) {
                v0 = fast_tanh(v0); v1 = fast_tanh(v1);
                v2 = fast_tanh(v2); v3 = fast_tanh(v3);
            }
            if (OUTH) {
                if (row0 < n) *(__half2*)(outh + (size_t)row0 * 128 + col) = __floats2half2_rn(v0, v1);
                if (row1 < n) *(__half2*)(outh + (size_t)row1 * 128 + col) = __floats2half2_rn(v2, v3);
            } else {
                if (row0 < n) *(float2*)(outf + (size_t)row0 * 128 + col) = make_float2(v0, v1);
                if (row1 < n) *(float2*)(outf + (size_t)row1 * 128 + col) = make_float2(v2, v3);
            }
        }
    }
}

// ---------------- final 128 -> 3 ----------------
__global__ void __launch_bounds__(256) out_k(
    const float* __restrict__ h, const float* __restrict__ lw4,
    const float* __restrict__ lb4, float* __restrict__ out, int n)
{
    int wid = (blockIdx.x * 256 + threadIdx.x) >> 5;
    int lane = threadIdx.x & 31;
    if (wid >= n) return;
    const float* row = h + (size_t)wid * 128;
    float a0 = 0.f, a1 = 0.f, a2 = 0.f;
    #pragma unroll
    for (int k = lane; k < 128; k += 32) {
        float hv = row[k];
        a0 = fmaf(hv, __ldg(&lw4[k * 3 + 0]), a0);
        a1 = fmaf(hv, __ldg(&lw4[k * 3 + 1]), a1);
        a2 = fmaf(hv, __ldg(&lw4[k * 3 + 2]), a2);
    }
    #pragma unroll
    for (int o = 16; o; o >>= 1) {
        a0 += __shfl_down_sync(0xffffffffu, a0, o);
        a1 += __shfl_down_sync(0xffffffffu, a1, o);
        a2 += __shfl_down_sync(0xffffffffu, a2, o);
    }
    if (lane == 0) {
        out[(size_t)wid * 3 + 0] = a0 + lb4[0];
        out[(size_t)wid * 3 + 1] = a1 + lb4[1];
        out[(size_t)wid * 3 + 2] = a2 + lb4[2];
    }
}

// ---------------- launch ----------------
extern "C" void kernel_launch(void* const* d_in, const int* in_sizes, int n_in,
                              void* d_out, int out_size)
{
    const float* x   = (const float*)d_in[0];
    const void*  ei  = d_in[1];
    const float* W1  = (const float*)d_in[2];
    const float* b1  = (const float*)d_in[3];
    const float* W2  = (const float*)d_in[4];
    const float* b2  = (const float*)d_in[5];
    const float* lw1 = (const float*)d_in[6];
    const float* lb1 = (const float*)d_in[7];
    const float* lw2 = (const float*)d_in[8];
    const float* lb2 = (const float*)d_in[9];
    const float* lw3 = (const float*)d_in[10];
    const float* lb3 = (const float*)d_in[11];
    const float* lw4 = (const float*)d_in[12];
    const float* lb4 = (const float*)d_in[13];
    float* out = (float*)d_out;

    int n = in_sizes[0] / H;
    long long E = (long long)in_sizes[1] / 2;

    float *pX, *pA, *pD, *pNrm;
    __half* pXh;
    int *pDeg, *pOff, *pCur, *pSrc;
    cudaGetSymbolAddress((void**)&pX, g_X);
    cudaGetSymbolAddress((void**)&pA, g_A);
    cudaGetSymbolAddress((void**)&pXh, g_Xh);
    cudaGetSymbolAddress((void**)&pD, g_dinv);
    cudaGetSymbolAddress((void**)&pDeg, g_deg);
    cudaGetSymbolAddress((void**)&pOff, g_off);
    cudaGetSymbolAddress((void**)&pCur, g_cur);
    cudaGetSymbolAddress((void**)&pSrc, g_csrc);
    cudaGetSymbolAddress((void**)&pNrm, g_cnrm);

    cudaFuncSetAttribute((const void*)gemm_tc<false, false, true>,
                         cudaFuncAttributeMaxDynamicSharedMemorySize, TC_SMEM);
    cudaFuncSetAttribute((const void*)gemm_tc<true, true, false>,
                         cudaFuncAttributeMaxDynamicSharedMemorySize, TC_SMEM);

    int gb  = (n + 127) / 128;             // gemm blocks
    int nwb = (n + 7) / 8;                 // warp-per-node blocks
    int eb  = (int)((E + 255) / 256);      // thread-per-edge blocks

    // Launch order keeps the conv1 GEMM at index 3 so ncu (-s 5 -c 1) profiles it.
    detect_k<<<1, 256>>>((const int*)ei);                                  // 0
    zeroi_k<<<(100352 / 4 + 255) / 256, 256>>>((int4*)pDeg, 100352 / 4);   // 1
    deg_k<<<eb, 256>>>(ei, E, pDeg);                                       // 2
    gemm_tc<false, false, true><<<gb, 512, TC_SMEM>>>(x, W1, nullptr, nullptr, pXh, n); // 3
    dinv_k<<<(n + 255) / 256, 256>>>(pDeg, pD, n);                         // 4
    scan_k<<<1, 1024>>>(pDeg, pOff, pCur, n);                              // 5
    fill_k<<<eb, 256>>>(ei, E, pD, pCur, pSrc, pNrm);                      // 6

    // conv1 aggregate: A = tanh(gather_fp16(Xh) + self + b1)   (fp32 out)
    aggregate_k<<<nwb, 256>>>(pXh, pOff, pDeg, pSrc, pNrm, pD, b1, pA, n);

    // conv2: Xh = A @ W2 (half out); X = tanh(gather(Xh) + self + b2)
    gemm_tc<false, false, true><<<gb, 512, TC_SMEM>>>(pA, W2, nullptr, nullptr, pXh, n);
    aggregate_k<<<nwb, 256>>>(pXh, pOff, pDeg, pSrc, pNrm, pD, b2, pX, n);

    // MLP head (fp32 path, r9 structure)
    gemm_tc<true, true, false><<<gb, 512, TC_SMEM>>>(pX, lw1, lb1, pA, nullptr, n);
    gemm_tc<true, true, false><<<gb, 512, TC_SMEM>>>(pA, lw2, lb2, pX, nullptr, n);
    gemm_tc<true, true, false><<<gb, 512, TC_SMEM>>>(pX, lw3, lb3, pA, nullptr, n);
    out_k<<<(n + 7) / 8, 256>>>(pA, lw4, lb4, out, n);
}

// round 12
// speedup vs baseline: 1.4139x; 1.4139x over previous
#include <cuda_runtime.h>
#include <cstdint>

#define NN 100000
#define EE 3200000
#define H 128

// ---------------- scratch (__device__ globals; allocation-free rule) ----------------
__device__ float g_X[(size_t)NN * H];   // 51.2 MB ping
__device__ float g_A[(size_t)NN * H];   // 51.2 MB pong
__device__ float g_dinv[NN];
__device__ int   g_deg[100352];         // padded for int4 zeroing
__device__ int   g_off[NN + 1];
__device__ int   g_cur[100352];
__device__ int   g_csrc[EE];            // CSR: src per incoming edge of dst
__device__ float g_cnrm[EE];            // CSR: norm per incoming edge
__device__ int   g_is64;

__device__ __forceinline__ float fast_tanh(float x) {
    float t = __expf(-2.0f * fabsf(x));
    float r = __fdividef(1.0f - t, 1.0f + t);
    return copysignf(r, x);
}

// ---------------- edge dtype detection (int32 vs int64) ----------------
__global__ void detect_k(const int* __restrict__ ei32) {
    __shared__ int nz;
    if (threadIdx.x == 0) nz = 0;
    __syncthreads();
    int c = 0;
    for (int k = threadIdx.x; k < 4096; k += blockDim.x)
        if (ei32[2 * k + 1] != 0) c++;
    atomicAdd(&nz, c);
    __syncthreads();
    if (threadIdx.x == 0) g_is64 = (nz == 0) ? 1 : 0;
}

__device__ __forceinline__ int edge_val(const void* ei, long long E, long long idx, int row) {
    if (g_is64) return (int)((const long long*)ei)[row ? E + idx : idx];
    return ((const int*)ei)[row ? E + idx : idx];
}

// ---------------- zero ints ----------------
__global__ void zeroi_k(int4* __restrict__ p, int n4) {
    int i = blockIdx.x * blockDim.x + threadIdx.x;
    if (i < n4) p[i] = make_int4(0, 0, 0, 0);
}

// ---------------- degree count ----------------
__global__ void deg_k(const void* __restrict__ ei, long long E, int* __restrict__ deg) {
    long long e = (long long)blockIdx.x * blockDim.x + threadIdx.x;
    if (e < E) atomicAdd(&deg[edge_val(ei, E, e, 1)], 1);
}

__global__ void dinv_k(const int* __restrict__ deg, float* __restrict__ dinv, int n) {
    int i = blockIdx.x * blockDim.x + threadIdx.x;
    if (i < n) dinv[i] = rsqrtf((float)deg[i] + 2.0f);   // improved self-loop: +2
}

// ---------------- single-block scan: deg -> off, cur ----------------
__global__ void __launch_bounds__(1024) scan_k(const int* __restrict__ deg,
                                               int* __restrict__ off,
                                               int* __restrict__ cur, int n) {
    __shared__ int part[1024];
    int t = threadIdx.x;
    int chunk = (n + 1023) / 1024;
    int lo = t * chunk, hi = lo + chunk < n ? lo + chunk : n;
    int s = 0;
    for (int i = lo; i < hi; i++) s += deg[i];
    part[t] = s;
    __syncthreads();
    for (int o = 1; o < 1024; o <<= 1) {
        int v = (t >= o) ? part[t - o] : 0;
        __syncthreads();
        part[t] += v;
        __syncthreads();
    }
    int base = (t == 0) ? 0 : part[t - 1];
    for (int i = lo; i < hi; i++) {
        off[i] = base; cur[i] = base; base += deg[i];
    }
    if (t == 0) off[n] = part[1023];
}

// ---------------- CSR fill ----------------
__global__ void fill_k(const void* __restrict__ ei, long long E,
                       const float* __restrict__ dinv,
                       int* __restrict__ cur, int* __restrict__ csrc,
                       float* __restrict__ cnrm) {
    long long e = (long long)blockIdx.x * blockDim.x + threadIdx.x;
    if (e >= E) return;
    int s = edge_val(ei, E, e, 0);
    int d = edge_val(ei, E, e, 1);
    int pos = atomicAdd(&cur[d], 1);
    csrc[pos] = s;
    cnrm[pos] = dinv[s] * dinv[d];
}

// ---------------- gather + conv epilogue: out = tanh(sum + xw*2dinv^2 + b) ----------------
__global__ void __launch_bounds__(256) aggregate_k(
    const float* __restrict__ xw, const int* __restrict__ off,
    const int* __restrict__ deg, const int* __restrict__ csrc,
    const float* __restrict__ cnrm, const float* __restrict__ dinv,
    const float* __restrict__ bias, float* __restrict__ out, int n)
{
    int node = (blockIdx.x * 256 + threadIdx.x) >> 5;
    int lane = threadIdx.x & 31;
    if (node >= n) return;
    int j = off[node];
    int end = j + deg[node];
    const float4* X4 = (const float4*)xw;
    float4 acc = make_float4(0.f, 0.f, 0.f, 0.f);
    for (; j + 1 < end; j += 2) {
        int s0 = __ldg(&csrc[j]);     int s1 = __ldg(&csrc[j + 1]);
        float n0 = __ldg(&cnrm[j]);   float n1 = __ldg(&cnrm[j + 1]);
        float4 v0 = X4[(size_t)s0 * 32 + lane];
        float4 v1 = X4[(size_t)s1 * 32 + lane];
        acc.x = fmaf(v0.x, n0, acc.x); acc.y = fmaf(v0.y, n0, acc.y);
        acc.z = fmaf(v0.z, n0, acc.z); acc.w = fmaf(v0.w, n0, acc.w);
        acc.x = fmaf(v1.x, n1, acc.x); acc.y = fmaf(v1.y, n1, acc.y);
        acc.z = fmaf(v1.z, n1, acc.z); acc.w = fmaf(v1.w, n1, acc.w);
    }
    if (j < end) {
        int s0 = __ldg(&csrc[j]);
        float n0 = __ldg(&cnrm[j]);
        float4 v0 = X4[(size_t)s0 * 32 + lane];
        acc.x = fmaf(v0.x, n0, acc.x); acc.y = fmaf(v0.y, n0, acc.y);
        acc.z = fmaf(v0.z, n0, acc.z); acc.w = fmaf(v0.w, n0, acc.w);
    }
    float di = dinv[node];
    float sw = 2.0f * di * di;
    float4 xv = X4[(size_t)node * 32 + lane];
    float4 bv = ((const float4*)bias)[lane];
    acc.x = fast_tanh(fmaf(xv.x, sw, acc.x) + bv.x);
    acc.y = fast_tanh(fmaf(xv.y, sw, acc.y) + bv.y);
    acc.z = fast_tanh(fmaf(xv.z, sw, acc.z) + bv.z);
    acc.w = fast_tanh(fmaf(xv.w, sw, acc.w) + bv.w);
    ((float4*)out)[(size_t)node * 32 + lane] = acc;
}

// ---------------- tf32 MMA common ----------------
#define ASTRIDE 132
#define WSTRIDE 136
// CTA tile 64 rows x 128 cols: A 64*132*4 + W 128*136*4 = 103424 B -> 2 CTAs/SM
#define TC_SMEM ((64 * ASTRIDE + 128 * WSTRIDE) * 4)

__device__ __forceinline__ float to_tf32(float x) {
    uint32_t u;
    asm("cvt.rna.tf32.f32 %0, %1;" : "=r"(u) : "f"(x));
    return __uint_as_float(u);
}

__device__ __forceinline__ void mma_tf32(float* c, const uint32_t* a,
                                         uint32_t b0, uint32_t b1) {
    asm volatile(
        "mma.sync.aligned.m16n8k8.row.col.f32.tf32.tf32.f32 "
        "{%0,%1,%2,%3}, {%4,%5,%6,%7}, {%8,%9}, {%0,%1,%2,%3};"
        : "+f"(c[0]), "+f"(c[1]), "+f"(c[2]), "+f"(c[3])
        : "r"(a[0]), "r"(a[1]), "r"(a[2]), "r"(a[3]), "r"(b0), "r"(b1));
}

// mainloop over one 32-row x 32-col warp tile (K=128)
__device__ __forceinline__ void mma_tile_128(
    const float* __restrict__ Asrc, const float* __restrict__ Wn,
    int strip, int nquart, int gid, int tg, float acc[2][4][4])
{
    #pragma unroll
    for (int r = 0; r < 2; r++)
        #pragma unroll
        for (int j = 0; j < 4; j++)
            #pragma unroll
            for (int q = 0; q < 4; q++) acc[r][j][q] = 0.f;

    const float* A0 = Asrc + (strip + gid) * ASTRIDE + tg;
    const float* B0 = Wn + tg * WSTRIDE + nquart + gid;

    #pragma unroll 4
    for (int ks = 0; ks < 16; ks++) {
        int k0 = ks * 8;
        uint32_t a[2][4];
        #pragma unroll
        for (int r = 0; r < 2; r++) {
            const float* p = A0 + r * 16 * ASTRIDE + k0;
            a[r][0] = __float_as_uint(p[0]);
            a[r][1] = __float_as_uint(p[8 * ASTRIDE]);
            a[r][2] = __float_as_uint(p[4]);
            a[r][3] = __float_as_uint(p[8 * ASTRIDE + 4]);
        }
        const float* q = B0 + k0 * WSTRIDE;
        #pragma unroll
        for (int j = 0; j < 4; j++) {
            uint32_t b0 = __float_as_uint(q[j * 8]);
            uint32_t b1 = __float_as_uint(q[4 * WSTRIDE + j * 8]);
            mma_tf32(acc[0][j], a[0], b0, b1);
            mma_tf32(acc[1][j], a[1], b0, b1);
        }
    }
}

// ---------------- GEMM [n,128]@[128,128]: CTA 64 rows, 256 thr, 2 CTAs/SM ------------
template <bool TANH, bool BIAS>
__global__ void __launch_bounds__(256) gemm_tc(
    const float* __restrict__ in, const float* __restrict__ W,
    const float* __restrict__ bias, float* __restrict__ out, int n)
{
    extern __shared__ float sm[];
    float* Asm = sm;                     // [64 rows][k] stride ASTRIDE
    float* Wn  = sm + 64 * ASTRIDE;      // [k][c] stride WSTRIDE

    int tid = threadIdx.x, lane = tid & 31, w = tid >> 5;
    int nb = blockIdx.x * 64;

    // stage A: 64 rows (tf32-rounded)
    const float4* In4 = (const float4*)in;
    #pragma unroll
    for (int i = tid; i < 2048; i += 256) {
        int row = i >> 5, q = i & 31;
        int node = nb + row < n ? nb + row : n - 1;
        float4 v = In4[(size_t)node * 32 + q];
        v.x = to_tf32(v.x); v.y = to_tf32(v.y);
        v.z = to_tf32(v.z); v.w = to_tf32(v.w);
        *(float4*)(Asm + row * ASTRIDE + q * 4) = v;
    }
    // stage W natural [k][c] (tf32-rounded)
    const float4* W4 = (const float4*)W;
    #pragma unroll
    for (int i = tid; i < 4096; i += 256) {
        int k = i >> 5, q = i & 31;
        float4 v = W4[k * 32 + q];
        v.x = to_tf32(v.x); v.y = to_tf32(v.y);
        v.z = to_tf32(v.z); v.w = to_tf32(v.w);
        *(float4*)(Wn + k * WSTRIDE + q * 4) = v;
    }
    __syncthreads();

    int strip  = (w >> 2) * 32;    // 0 or 32
    int nquart = (w & 3) * 32;     // 0,32,64,96
    int gid = lane >> 2, tg = lane & 3;

    float acc[2][4][4];
    mma_tile_128(Asm, Wn, strip, nquart, gid, tg, acc);

    #pragma unroll
    for (int j = 0; j < 4; j++) {
        int col = nquart + 8 * j + 2 * tg;
        float2 bv = BIAS ? __ldg((const float2*)(bias + col)) : make_float2(0.f, 0.f);
        #pragma unroll
        for (int r = 0; r < 2; r++) {
            int row0 = nb + strip + r * 16 + gid;
            int row1 = row0 + 8;
            float v0 = acc[r][j][0] + bv.x;
            float v1 = acc[r][j][1] + bv.y;
            float v2 = acc[r][j][2] + bv.x;
            float v3 = acc[r][j][3] + bv.y;
            if (TANH) {
                v0 = fast_tanh(v0); v1 = fast_tanh(v1);
                v2 = fast_tanh(v2); v3 = fast_tanh(v3);
            }
            if (row0 < n) *(float2*)(out + (size_t)row0 * 128 + col) = make_float2(v0, v1);
            if (row1 < n) *(float2*)(out + (size_t)row1 * 128 + col) = make_float2(v2, v3);
        }
    }
}

// ---------------- final 128 -> 3 ----------------
__global__ void __launch_bounds__(256) out_k(
    const float* __restrict__ h, const float* __restrict__ lw4,
    const float* __restrict__ lb4, float* __restrict__ out, int n)
{
    int wid = (blockIdx.x * 256 + threadIdx.x) >> 5;
    int lane = threadIdx.x & 31;
    if (wid >= n) return;
    const float* row = h + (size_t)wid * 128;
    float a0 = 0.f, a1 = 0.f, a2 = 0.f;
    #pragma unroll
    for (int k = lane; k < 128; k += 32) {
        float hv = row[k];
        a0 = fmaf(hv, __ldg(&lw4[k * 3 + 0]), a0);
        a1 = fmaf(hv, __ldg(&lw4[k * 3 + 1]), a1);
        a2 = fmaf(hv, __ldg(&lw4[k * 3 + 2]), a2);
    }
    #pragma unroll
    for (int o = 16; o; o >>= 1) {
        a0 += __shfl_down_sync(0xffffffffu, a0, o);
        a1 += __shfl_down_sync(0xffffffffu, a1, o);
        a2 += __shfl_down_sync(0xffffffffu, a2, o);
    }
    if (lane == 0) {
        out[(size_t)wid * 3 + 0] = a0 + lb4[0];
        out[(size_t)wid * 3 + 1] = a1 + lb4[1];
        out[(size_t)wid * 3 + 2] = a2 + lb4[2];
    }
}

// ---------------- launch ----------------
extern "C" void kernel_launch(void* const* d_in, const int* in_sizes, int n_in,
                              void* d_out, int out_size)
{
    const float* x   = (const float*)d_in[0];
    const void*  ei  = d_in[1];
    const float* W1  = (const float*)d_in[2];
    const float* b1  = (const float*)d_in[3];
    const float* W2  = (const float*)d_in[4];
    const float* b2  = (const float*)d_in[5];
    const float* lw1 = (const float*)d_in[6];
    const float* lb1 = (const float*)d_in[7];
    const float* lw2 = (const float*)d_in[8];
    const float* lb2 = (const float*)d_in[9];
    const float* lw3 = (const float*)d_in[10];
    const float* lb3 = (const float*)d_in[11];
    const float* lw4 = (const float*)d_in[12];
    const float* lb4 = (const float*)d_in[13];
    float* out = (float*)d_out;

    int n = in_sizes[0] / H;
    long long E = (long long)in_sizes[1] / 2;

    float *pX, *pA, *pD, *pNrm;
    int *pDeg, *pOff, *pCur, *pSrc;
    cudaGetSymbolAddress((void**)&pX, g_X);
    cudaGetSymbolAddress((void**)&pA, g_A);
    cudaGetSymbolAddress((void**)&pD, g_dinv);
    cudaGetSymbolAddress((void**)&pDeg, g_deg);
    cudaGetSymbolAddress((void**)&pOff, g_off);
    cudaGetSymbolAddress((void**)&pCur, g_cur);
    cudaGetSymbolAddress((void**)&pSrc, g_csrc);
    cudaGetSymbolAddress((void**)&pNrm, g_cnrm);

    cudaFuncSetAttribute(gemm_tc<false, false>, cudaFuncAttributeMaxDynamicSharedMemorySize, TC_SMEM);
    cudaFuncSetAttribute(gemm_tc<true,  true>,  cudaFuncAttributeMaxDynamicSharedMemorySize, TC_SMEM);

    int gb  = (n + 63) / 64;               // gemm blocks (64-row tiles)
    int nwb = (n + 7) / 8;                 // warp-per-node blocks
    int eb  = (int)((E + 255) / 256);      // thread-per-edge blocks

    // Launch order keeps the conv1 GEMM at index 3 so ncu (-s 5 -c 1) profiles it.
    detect_k<<<1, 256>>>((const int*)ei);                                  // 0
    zeroi_k<<<(100352 / 4 + 255) / 256, 256>>>((int4*)pDeg, 100352 / 4);   // 1
    deg_k<<<eb, 256>>>(ei, E, pDeg);                                       // 2
    gemm_tc<false, false><<<gb, 256, TC_SMEM>>>(x, W1, nullptr, pX, n);    // 3 <- profiled
    dinv_k<<<(n + 255) / 256, 256>>>(pDeg, pD, n);                         // 4
    scan_k<<<1, 1024>>>(pDeg, pOff, pCur, n);                              // 5
    fill_k<<<eb, 256>>>(ei, E, pD, pCur, pSrc, pNrm);                      // 6

    // conv1 aggregate
    aggregate_k<<<nwb, 256>>>(pX, pOff, pDeg, pSrc, pNrm, pD, b1, pA, n);

    // conv2
    gemm_tc<false, false><<<gb, 256, TC_SMEM>>>(pA, W2, nullptr, pX, n);
    aggregate_k<<<nwb, 256>>>(pX, pOff, pDeg, pSrc, pNrm, pD, b2, pA, n);

    // MLP head
    gemm_tc<true, true><<<gb, 256, TC_SMEM>>>(pA, lw1, lb1, pX, n);
    gemm_tc<true, true><<<gb, 256, TC_SMEM>>>(pX, lw2, lb2, pA, n);
    gemm_tc<true, true><<<gb, 256, TC_SMEM>>>(pA, lw3, lb3, pX, n);
    out_k<<<(n + 7) / 8, 256>>>(pX, lw4, lb4, out, n);
}

// round 14
// speedup vs baseline: 1.5270x; 1.0801x over previous
#include <cuda_runtime.h>
#include <cuda_fp16.h>
#include <cstdint>

#define NN 100000
#define EE 3200000
#define H 128

// ---------------- scratch (__device__ globals; allocation-free rule) ----------------
__device__ float  g_X[(size_t)NN * H];    // 51.2 MB fp32 ping
__device__ float  g_A[(size_t)NN * H];    // 51.2 MB fp32 pong
__device__ __half g_Xh[(size_t)NN * H];   // 25.6 MB fp16 conv-GEMM out (gather source)
__device__ float  g_dinv[NN];
__device__ int    g_deg[100352];          // padded for int4 zeroing
__device__ int    g_off[NN + 1];
__device__ int    g_cur[100352];
__device__ int    g_csrc[EE];             // CSR: src per incoming edge of dst
__device__ float  g_cnrm[EE];             // CSR: norm per incoming edge
__device__ int    g_is64;

__device__ __forceinline__ float fast_tanh(float x) {
    float t = __expf(-2.0f * fabsf(x));
    float r = __fdividef(1.0f - t, 1.0f + t);
    return copysignf(r, x);
}

// ---------------- edge dtype detection (int32 vs int64) ----------------
__global__ void detect_k(const int* __restrict__ ei32) {
    __shared__ int nz;
    if (threadIdx.x == 0) nz = 0;
    __syncthreads();
    int c = 0;
    for (int k = threadIdx.x; k < 4096; k += blockDim.x)
        if (ei32[2 * k + 1] != 0) c++;
    atomicAdd(&nz, c);
    __syncthreads();
    if (threadIdx.x == 0) g_is64 = (nz == 0) ? 1 : 0;
}

__device__ __forceinline__ int edge_val(const void* ei, long long E, long long idx, int row) {
    if (g_is64) return (int)((const long long*)ei)[row ? E + idx : idx];
    return ((const int*)ei)[row ? E + idx : idx];
}

// ---------------- zero ints ----------------
__global__ void zeroi_k(int4* __restrict__ p, int n4) {
    int i = blockIdx.x * blockDim.x + threadIdx.x;
    if (i < n4) p[i] = make_int4(0, 0, 0, 0);
}

// ---------------- degree count ----------------
__global__ void deg_k(const void* __restrict__ ei, long long E, int* __restrict__ deg) {
    long long e = (long long)blockIdx.x * blockDim.x + threadIdx.x;
    if (e < E) atomicAdd(&deg[edge_val(ei, E, e, 1)], 1);
}

__global__ void dinv_k(const int* __restrict__ deg, float* __restrict__ dinv, int n) {
    int i = blockIdx.x * blockDim.x + threadIdx.x;
    if (i < n) dinv[i] = rsqrtf((float)deg[i] + 2.0f);   // improved self-loop: +2
}

// ---------------- single-block scan: deg -> off, cur ----------------
__global__ void __launch_bounds__(1024) scan_k(const int* __restrict__ deg,
                                               int* __restrict__ off,
                                               int* __restrict__ cur, int n) {
    __shared__ int part[1024];
    int t = threadIdx.x;
    int chunk = (n + 1023) / 1024;
    int lo = t * chunk, hi = lo + chunk < n ? lo + chunk : n;
    int s = 0;
    for (int i = lo; i < hi; i++) s += deg[i];
    part[t] = s;
    __syncthreads();
    for (int o = 1; o < 1024; o <<= 1) {
        int v = (t >= o) ? part[t - o] : 0;
        __syncthreads();
        part[t] += v;
        __syncthreads();
    }
    int base = (t == 0) ? 0 : part[t - 1];
    for (int i = lo; i < hi; i++) {
        off[i] = base; cur[i] = base; base += deg[i];
    }
    if (t == 0) off[n] = part[1023];
}

// ---------------- CSR fill ----------------
__global__ void fill_k(const void* __restrict__ ei, long long E,
                       const float* __restrict__ dinv,
                       int* __restrict__ cur, int* __restrict__ csrc,
                       float* __restrict__ cnrm) {
    long long e = (long long)blockIdx.x * blockDim.x + threadIdx.x;
    if (e >= E) return;
    int s = edge_val(ei, E, e, 0);
    int d = edge_val(ei, E, e, 1);
    int pos = atomicAdd(&cur[d], 1);
    csrc[pos] = s;
    cnrm[pos] = dinv[s] * dinv[d];
}

// ---------------- gather (fp16 rows, 256B) + conv epilogue ----------------
// out_fp32 = tanh(sum_edges(norm * xh[src]) + xh[node]*2dinv^2 + b)
__global__ void __launch_bounds__(256) aggregate_k(
    const __half* __restrict__ xw, const int* __restrict__ off,
    const int* __restrict__ deg, const int* __restrict__ csrc,
    const float* __restrict__ cnrm, const float* __restrict__ dinv,
    const float* __restrict__ bias, float* __restrict__ out, int n)
{
    int node = (blockIdx.x * 256 + threadIdx.x) >> 5;
    int lane = threadIdx.x & 31;
    if (node >= n) return;
    int j = off[node];
    int end = j + deg[node];
    const uint2* X2 = (const uint2*)xw;   // 8B = 4 halves per lane
    float4 acc = make_float4(0.f, 0.f, 0.f, 0.f);
    for (; j + 1 < end; j += 2) {
        int s0 = __ldg(&csrc[j]);     int s1 = __ldg(&csrc[j + 1]);
        float n0 = __ldg(&cnrm[j]);   float n1 = __ldg(&cnrm[j + 1]);
        uint2 r0 = X2[(size_t)s0 * 32 + lane];
        uint2 r1 = X2[(size_t)s1 * 32 + lane];
        float2 a01 = __half22float2(*(__half2*)&r0.x);
        float2 a23 = __half22float2(*(__half2*)&r0.y);
        float2 b01 = __half22float2(*(__half2*)&r1.x);
        float2 b23 = __half22float2(*(__half2*)&r1.y);
        acc.x = fmaf(a01.x, n0, acc.x); acc.y = fmaf(a01.y, n0, acc.y);
        acc.z = fmaf(a23.x, n0, acc.z); acc.w = fmaf(a23.y, n0, acc.w);
        acc.x = fmaf(b01.x, n1, acc.x); acc.y = fmaf(b01.y, n1, acc.y);
        acc.z = fmaf(b23.x, n1, acc.z); acc.w = fmaf(b23.y, n1, acc.w);
    }
    if (j < end) {
        int s0 = __ldg(&csrc[j]);
        float n0 = __ldg(&cnrm[j]);
        uint2 r0 = X2[(size_t)s0 * 32 + lane];
        float2 a01 = __half22float2(*(__half2*)&r0.x);
        float2 a23 = __half22float2(*(__half2*)&r0.y);
        acc.x = fmaf(a01.x, n0, acc.x); acc.y = fmaf(a01.y, n0, acc.y);
        acc.z = fmaf(a23.x, n0, acc.z); acc.w = fmaf(a23.y, n0, acc.w);
    }
    float di = dinv[node];
    float sw = 2.0f * di * di;
    uint2 rs = X2[(size_t)node * 32 + lane];
    float2 s01 = __half22float2(*(__half2*)&rs.x);
    float2 s23 = __half22float2(*(__half2*)&rs.y);
    float4 bv = ((const float4*)bias)[lane];
    acc.x = fast_tanh(fmaf(s01.x, sw, acc.x) + bv.x);
    acc.y = fast_tanh(fmaf(s01.y, sw, acc.y) + bv.y);
    acc.z = fast_tanh(fmaf(s23.x, sw, acc.z) + bv.z);
    acc.w = fast_tanh(fmaf(s23.y, sw, acc.w) + bv.w);
    ((float4*)out)[(size_t)node * 32 + lane] = acc;
}

// ---------------- tf32 MMA common ----------------
#define ASTRIDE 132
#define WSTRIDE 136
// CTA tile 64 rows x 128 cols: A 64*132*4 + W 128*136*4 = 103424 B -> 2 CTAs/SM
#define TC_SMEM ((64 * ASTRIDE + 128 * WSTRIDE) * 4)
#define HSTRIDE 136    // halves per row in fp16 staging buffer: 272B = 16B-aligned rows

__device__ __forceinline__ float to_tf32(float x) {
    uint32_t u;
    asm("cvt.rna.tf32.f32 %0, %1;" : "=r"(u) : "f"(x));
    return __uint_as_float(u);
}

__device__ __forceinline__ void mma_tf32(float* c, const uint32_t* a,
                                         uint32_t b0, uint32_t b1) {
    asm volatile(
        "mma.sync.aligned.m16n8k8.row.col.f32.tf32.tf32.f32 "
        "{%0,%1,%2,%3}, {%4,%5,%6,%7}, {%8,%9}, {%0,%1,%2,%3};"
        : "+f"(c[0]), "+f"(c[1]), "+f"(c[2]), "+f"(c[3])
        : "r"(a[0]), "r"(a[1]), "r"(a[2]), "r"(a[3]), "r"(b0), "r"(b1));
}

// mainloop over one 32-row x 32-col warp tile (K=128)
__device__ __forceinline__ void mma_tile_128(
    const float* __restrict__ Asrc, const float* __restrict__ Wn,
    int strip, int nquart, int gid, int tg, float acc[2][4][4])
{
    #pragma unroll
    for (int r = 0; r < 2; r++)
        #pragma unroll
        for (int j = 0; j < 4; j++)
            #pragma unroll
            for (int q = 0; q < 4; q++) acc[r][j][q] = 0.f;

    const float* A0 = Asrc + (strip + gid) * ASTRIDE + tg;
    const float* B0 = Wn + tg * WSTRIDE + nquart + gid;

    #pragma unroll 4
    for (int ks = 0; ks < 16; ks++) {
        int k0 = ks * 8;
        uint32_t a[2][4];
        #pragma unroll
        for (int r = 0; r < 2; r++) {
            const float* p = A0 + r * 16 * ASTRIDE + k0;
            a[r][0] = __float_as_uint(p[0]);
            a[r][1] = __float_as_uint(p[8 * ASTRIDE]);
            a[r][2] = __float_as_uint(p[4]);
            a[r][3] = __float_as_uint(p[8 * ASTRIDE + 4]);
        }
        const float* q = B0 + k0 * WSTRIDE;
        #pragma unroll
        for (int j = 0; j < 4; j++) {
            uint32_t b0 = __float_as_uint(q[j * 8]);
            uint32_t b1 = __float_as_uint(q[4 * WSTRIDE + j * 8]);
            mma_tf32(acc[0][j], a[0], b0, b1);
            mma_tf32(acc[1][j], a[1], b0, b1);
        }
    }
}

// ---------------- GEMM [n,128]@[128,128]: CTA 64 rows, 256 thr ------------
// OUTH=1: fp16 output staged via smem for coalesced STG.128.
template <bool TANH, bool BIAS, bool OUTH>
__global__ void __launch_bounds__(256) gemm_tc(
    const float* __restrict__ in, const float* __restrict__ W,
    const float* __restrict__ bias, float* __restrict__ outf,
    __half* __restrict__ outh, int n)
{
    extern __shared__ float sm[];
    float* Asm = sm;                     // [64 rows][k] stride ASTRIDE
    float* Wn  = sm + 64 * ASTRIDE;      // [k][c] stride WSTRIDE

    int tid = threadIdx.x, lane = tid & 31, w = tid >> 5;
    int nb = blockIdx.x * 64;

    // stage A: 64 rows (tf32-rounded)
    const float4* In4 = (const float4*)in;
    #pragma unroll
    for (int i = tid; i < 2048; i += 256) {
        int row = i >> 5, q = i & 31;
        int node = nb + row < n ? nb + row : n - 1;
        float4 v = In4[(size_t)node * 32 + q];
        v.x = to_tf32(v.x); v.y = to_tf32(v.y);
        v.z = to_tf32(v.z); v.w = to_tf32(v.w);
        *(float4*)(Asm + row * ASTRIDE + q * 4) = v;
    }
    // stage W natural [k][c] (tf32-rounded)
    const float4* W4 = (const float4*)W;
    #pragma unroll
    for (int i = tid; i < 4096; i += 256) {
        int k = i >> 5, q = i & 31;
        float4 v = W4[k * 32 + q];
        v.x = to_tf32(v.x); v.y = to_tf32(v.y);
        v.z = to_tf32(v.z); v.w = to_tf32(v.w);
        *(float4*)(Wn + k * WSTRIDE + q * 4) = v;
    }
    __syncthreads();

    int strip  = (w >> 2) * 32;    // 0 or 32
    int nquart = (w & 3) * 32;     // 0,32,64,96
    int gid = lane >> 2, tg = lane & 3;

    float acc[2][4][4];
    mma_tile_128(Asm, Wn, strip, nquart, gid, tg, acc);

    if (OUTH) {
        // stage fp16 tile in smem (reuse Asm region), then coalesced STG.128
        __syncthreads();                  // everyone done reading Asm
        __half* Hs = (__half*)Asm;        // [64][HSTRIDE] halves, 272B rows
        #pragma unroll
        for (int j = 0; j < 4; j++) {
            int col = nquart + 8 * j + 2 * tg;
            #pragma unroll
            for (int r = 0; r < 2; r++) {
                int row0 = strip + r * 16 + gid;
                *(__half2*)(Hs + row0 * HSTRIDE + col) =
                    __floats2half2_rn(acc[r][j][0], acc[r][j][1]);
                *(__half2*)(Hs + (row0 + 8) * HSTRIDE + col) =
                    __floats2half2_rn(acc[r][j][2], acc[r][j][3]);
            }
        }
        __syncthreads();
        // 64 rows x 128 halves: 16B chunks, 1024 chunks total, 4 iters
        #pragma unroll
        for (int i = tid; i < 1024; i += 256) {
            int row = i >> 4, c8 = (i & 15) * 8;
            uint4 v = *(uint4*)(Hs + row * HSTRIDE + c8);
            int node = nb + row;
            if (node < n) *(uint4*)(outh + (size_t)node * 128 + c8) = v;
        }
    } else {
        #pragma unroll
        for (int j = 0; j < 4; j++) {
            int col = nquart + 8 * j + 2 * tg;
            float2 bv = BIAS ? __ldg((const float2*)(bias + col)) : make_float2(0.f, 0.f);
            #pragma unroll
            for (int r = 0; r < 2; r++) {
                int row0 = nb + strip + r * 16 + gid;
                int row1 = row0 + 8;
                float v0 = acc[r][j][0] + bv.x;
                float v1 = acc[r][j][1] + bv.y;
                float v2 = acc[r][j][2] + bv.x;
                float v3 = acc[r][j][3] + bv.y;
                if (TANH) {
                    v0 = fast_tanh(v0); v1 = fast_tanh(v1);
                    v2 = fast_tanh(v2); v3 = fast_tanh(v3);
                }
                if (row0 < n) *(float2*)(outf + (size_t)row0 * 128 + col) = make_float2(v0, v1);
                if (row1 < n) *(float2*)(outf + (size_t)row1 * 128 + col) = make_float2(v2, v3);
            }
        }
    }
}

// ---------------- final 128 -> 3 ----------------
__global__ void __launch_bounds__(256) out_k(
    const float* __restrict__ h, const float* __restrict__ lw4,
    const float* __restrict__ lb4, float* __restrict__ out, int n)
{
    int wid = (blockIdx.x * 256 + threadIdx.x) >> 5;
    int lane = threadIdx.x & 31;
    if (wid >= n) return;
    const float* row = h + (size_t)wid * 128;
    float a0 = 0.f, a1 = 0.f, a2 = 0.f;
    #pragma unroll
    for (int k = lane; k < 128; k += 32) {
        float hv = row[k];
        a0 = fmaf(hv, __ldg(&lw4[k * 3 + 0]), a0);
        a1 = fmaf(hv, __ldg(&lw4[k * 3 + 1]), a1);
        a2 = fmaf(hv, __ldg(&lw4[k * 3 + 2]), a2);
    }
    #pragma unroll
    for (int o = 16; o; o >>= 1) {
        a0 += __shfl_down_sync(0xffffffffu, a0, o);
        a1 += __shfl_down_sync(0xffffffffu, a1, o);
        a2 += __shfl_down_sync(0xffffffffu, a2, o);
    }
    if (lane == 0) {
        out[(size_t)wid * 3 + 0] = a0 + lb4[0];
        out[(size_t)wid * 3 + 1] = a1 + lb4[1];
        out[(size_t)wid * 3 + 2] = a2 + lb4[2];
    }
}

// ---------------- launch ----------------
extern "C" void kernel_launch(void* const* d_in, const int* in_sizes, int n_in,
                              void* d_out, int out_size)
{
    const float* x   = (const float*)d_in[0];
    const void*  ei  = d_in[1];
    const float* W1  = (const float*)d_in[2];
    const float* b1  = (const float*)d_in[3];
    const float* W2  = (const float*)d_in[4];
    const float* b2  = (const float*)d_in[5];
    const float* lw1 = (const float*)d_in[6];
    const float* lb1 = (const float*)d_in[7];
    const float* lw2 = (const float*)d_in[8];
    const float* lb2 = (const float*)d_in[9];
    const float* lw3 = (const float*)d_in[10];
    const float* lb3 = (const float*)d_in[11];
    const float* lw4 = (const float*)d_in[12];
    const float* lb4 = (const float*)d_in[13];
    float* out = (float*)d_out;

    int n = in_sizes[0] / H;
    long long E = (long long)in_sizes[1] / 2;

    float *pX, *pA, *pD, *pNrm;
    __half* pXh;
    int *pDeg, *pOff, *pCur, *pSrc;
    cudaGetSymbolAddress((void**)&pX, g_X);
    cudaGetSymbolAddress((void**)&pA, g_A);
    cudaGetSymbolAddress((void**)&pXh, g_Xh);
    cudaGetSymbolAddress((void**)&pD, g_dinv);
    cudaGetSymbolAddress((void**)&pDeg, g_deg);
    cudaGetSymbolAddress((void**)&pOff, g_off);
    cudaGetSymbolAddress((void**)&pCur, g_cur);
    cudaGetSymbolAddress((void**)&pSrc, g_csrc);
    cudaGetSymbolAddress((void**)&pNrm, g_cnrm);

    cudaFuncSetAttribute((const void*)gemm_tc<false, false, true>,
                         cudaFuncAttributeMaxDynamicSharedMemorySize, TC_SMEM);
    cudaFuncSetAttribute((const void*)gemm_tc<true, true, false>,
                         cudaFuncAttributeMaxDynamicSharedMemorySize, TC_SMEM);

    int gb  = (n + 63) / 64;               // gemm blocks (64-row tiles)
    int nwb = (n + 7) / 8;                 // warp-per-node blocks
    int eb  = (int)((E + 255) / 256);      // thread-per-edge blocks

    // Launch order keeps the conv1 GEMM at index 3 so ncu (-s 5 -c 1) profiles it.
    detect_k<<<1, 256>>>((const int*)ei);                                  // 0
    zeroi_k<<<(100352 / 4 + 255) / 256, 256>>>((int4*)pDeg, 100352 / 4);   // 1
    deg_k<<<eb, 256>>>(ei, E, pDeg);                                       // 2
    gemm_tc<false, false, true><<<gb, 256, TC_SMEM>>>(x, W1, nullptr, nullptr, pXh, n); // 3
    dinv_k<<<(n + 255) / 256, 256>>>(pDeg, pD, n);                         // 4
    scan_k<<<1, 1024>>>(pDeg, pOff, pCur, n);                              // 5
    fill_k<<<eb, 256>>>(ei, E, pD, pCur, pSrc, pNrm);                      // 6

    // conv1 aggregate: A = tanh(gather_fp16(Xh) + self + b1)  (fp32 out)
    aggregate_k<<<nwb, 256>>>(pXh, pOff, pDeg, pSrc, pNrm, pD, b1, pA, n);

    // conv2: Xh = A @ W2 (fp16 out); X = tanh(gather(Xh) + self + b2)
    gemm_tc<false, false, true><<<gb, 256, TC_SMEM>>>(pA, W2, nullptr, nullptr, pXh, n);
    aggregate_k<<<nwb, 256>>>(pXh, pOff, pDeg, pSrc, pNrm, pD, b2, pX, n);

    // MLP head (fp32, r12 structure)
    gemm_tc<true, true, false><<<gb, 256, TC_SMEM>>>(pX, lw1, lb1, pA, nullptr, n);
    gemm_tc<true, true, false><<<gb, 256, TC_SMEM>>>(pA, lw2, lb2, pX, nullptr, n);
    gemm_tc<true, true, false><<<gb, 256, TC_SMEM>>>(pX, lw3, lb3, pA, nullptr, n);
    out_k<<<(n + 7) / 8, 256>>>(pA, lw4, lb4, out, n);
}